// round 1
// baseline (speedup 1.0000x reference)
#include <cuda_runtime.h>
#include <math.h>

// Problem constants
constexpr int B_   = 8;
constexpr int N_   = 1025;
constexpr int H_   = 12;
constexpr int HD_  = 64;
constexpr int DIM_ = 768;
constexpr int NTOK = B_ * N_;     // 8200
constexpr int C3   = 3 * DIM_;    // 2304
constexpr int BH   = B_ * H_;     // 96
constexpr float SCALE = 0.125f;   // hd^-0.5

// Scratch (device globals; no dynamic allocation allowed)
__device__ float g_Q[(size_t)BH * N_ * HD_];   // unroped, then roped in place (row n=0 untouched)
__device__ float g_K[(size_t)BH * N_ * HD_];
__device__ float g_V[(size_t)BH * N_ * HD_];
__device__ float g_col0[BH * N_];              // unroped q_i . k_cls
__device__ float g_row0[BH * N_];              // unroped q_cls . k_j
__device__ float g_att[(size_t)NTOK * DIM_];   // attention output, (b,n, h*64+d)

// ---------------------------------------------------------------------------
// Tiled fp32 GEMM: C(M,Ncol) = A(M,K) @ W(Ncol,K)^T
// BM=BN=128, BK=16, TM=TN=8, 256 threads
// ---------------------------------------------------------------------------
constexpr int BM = 128, BNt = 128, BK = 16, TM = 8, TN = 8;

__global__ void __launch_bounds__(256) qkv_gemm_kernel(const float* __restrict__ A,
                                                       const float* __restrict__ W) {
    __shared__ float As[BK][BM];
    __shared__ float Bs[BK][BNt];
    const int bm = blockIdx.y * BM;
    const int bn = blockIdx.x * BNt;
    const int tid = threadIdx.x;
    const int lr = tid >> 2;         // 0..63
    const int lc = (tid & 3) << 2;   // 0,4,8,12
    const int ty = tid >> 4;         // 0..15
    const int tx = tid & 15;

    float acc[TM][TN];
    #pragma unroll
    for (int i = 0; i < TM; i++)
        #pragma unroll
        for (int j = 0; j < TN; j++) acc[i][j] = 0.f;

    for (int k0 = 0; k0 < DIM_; k0 += BK) {
        #pragma unroll
        for (int it = 0; it < 2; it++) {
            int m = lr + it * 64;
            int gm = bm + m;
            float4 v = make_float4(0.f, 0.f, 0.f, 0.f);
            if (gm < NTOK) v = *(const float4*)&A[gm * DIM_ + k0 + lc];
            As[lc + 0][m] = v.x; As[lc + 1][m] = v.y;
            As[lc + 2][m] = v.z; As[lc + 3][m] = v.w;
            int n = lr + it * 64;
            float4 w = *(const float4*)&W[(bn + n) * DIM_ + k0 + lc];
            Bs[lc + 0][n] = w.x; Bs[lc + 1][n] = w.y;
            Bs[lc + 2][n] = w.z; Bs[lc + 3][n] = w.w;
        }
        __syncthreads();
        #pragma unroll
        for (int kk = 0; kk < BK; kk++) {
            float a[TM], b[TN];
            #pragma unroll
            for (int i = 0; i < TM; i++) a[i] = As[kk][ty * TM + i];
            #pragma unroll
            for (int j = 0; j < TN; j++) b[j] = Bs[kk][tx * TN + j];
            #pragma unroll
            for (int i = 0; i < TM; i++)
                #pragma unroll
                for (int j = 0; j < TN; j++)
                    acc[i][j] = fmaf(a[i], b[j], acc[i][j]);
        }
        __syncthreads();
    }

    // Scatter epilogue: c = which*768 + h*64 + d  ->  g_{Q,K,V}[bh][n][d]
    #pragma unroll
    for (int i = 0; i < TM; i++) {
        int gm = bm + ty * TM + i;
        if (gm >= NTOK) continue;
        int b = gm / N_, n = gm - b * N_;
        #pragma unroll
        for (int j = 0; j < TN; j++) {
            int gc = bn + tx * TN + j;
            int which = gc / DIM_;
            int rem = gc - which * DIM_;
            int h = rem >> 6;
            int d = rem & 63;
            float* dst = (which == 0) ? g_Q : (which == 1) ? g_K : g_V;
            dst[(size_t)((b * H_ + h) * N_ + n) * HD_ + d] = acc[i][j];
        }
    }
}

__global__ void __launch_bounds__(256) proj_gemm_kernel(const float* __restrict__ W,
                                                        const float* __restrict__ bias,
                                                        float* __restrict__ out) {
    __shared__ float As[BK][BM];
    __shared__ float Bs[BK][BNt];
    const float* A = g_att;
    const int bm = blockIdx.y * BM;
    const int bn = blockIdx.x * BNt;
    const int tid = threadIdx.x;
    const int lr = tid >> 2;
    const int lc = (tid & 3) << 2;
    const int ty = tid >> 4;
    const int tx = tid & 15;

    float acc[TM][TN];
    #pragma unroll
    for (int i = 0; i < TM; i++)
        #pragma unroll
        for (int j = 0; j < TN; j++) acc[i][j] = 0.f;

    for (int k0 = 0; k0 < DIM_; k0 += BK) {
        #pragma unroll
        for (int it = 0; it < 2; it++) {
            int m = lr + it * 64;
            int gm = bm + m;
            float4 v = make_float4(0.f, 0.f, 0.f, 0.f);
            if (gm < NTOK) v = *(const float4*)&A[(size_t)gm * DIM_ + k0 + lc];
            As[lc + 0][m] = v.x; As[lc + 1][m] = v.y;
            As[lc + 2][m] = v.z; As[lc + 3][m] = v.w;
            int n = lr + it * 64;
            float4 w = *(const float4*)&W[(bn + n) * DIM_ + k0 + lc];
            Bs[lc + 0][n] = w.x; Bs[lc + 1][n] = w.y;
            Bs[lc + 2][n] = w.z; Bs[lc + 3][n] = w.w;
        }
        __syncthreads();
        #pragma unroll
        for (int kk = 0; kk < BK; kk++) {
            float a[TM], b[TN];
            #pragma unroll
            for (int i = 0; i < TM; i++) a[i] = As[kk][ty * TM + i];
            #pragma unroll
            for (int j = 0; j < TN; j++) b[j] = Bs[kk][tx * TN + j];
            #pragma unroll
            for (int i = 0; i < TM; i++)
                #pragma unroll
                for (int j = 0; j < TN; j++)
                    acc[i][j] = fmaf(a[i], b[j], acc[i][j]);
        }
        __syncthreads();
    }

    #pragma unroll
    for (int i = 0; i < TM; i++) {
        int gm = bm + ty * TM + i;
        if (gm >= NTOK) continue;
        #pragma unroll
        for (int j = 0; j < TN; j++) {
            int gc = bn + tx * TN + j;
            out[(size_t)gm * DIM_ + gc] = acc[i][j] + bias[gc];
        }
    }
}

// ---------------------------------------------------------------------------
// cls scores: MUST run before rope (uses unroped Q/K)
// col0[bh,i] = Q[bh,i,:] . K[bh,0,:]   ;   row0[bh,j] = Q[bh,0,:] . K[bh,j,:]
// one warp per row index; float2 per lane; shfl reduce
// ---------------------------------------------------------------------------
__global__ void __launch_bounds__(256) cls_kernel() {
    int bh = blockIdx.x;
    int warp = threadIdx.x >> 5, lane = threadIdx.x & 31;
    int i = blockIdx.y * 8 + warp;
    if (i >= N_) return;
    const float2* Qi = (const float2*)(g_Q + ((size_t)bh * N_ + i) * HD_);
    const float2* K0 = (const float2*)(g_K + (size_t)bh * N_ * HD_);
    const float2* Q0 = (const float2*)(g_Q + (size_t)bh * N_ * HD_);
    const float2* Ki = (const float2*)(g_K + ((size_t)bh * N_ + i) * HD_);
    float2 a = Qi[lane], b0 = K0[lane], c = Q0[lane], d = Ki[lane];
    float s = a.x * b0.x + a.y * b0.y;
    float r = c.x * d.x + c.y * d.y;
    #pragma unroll
    for (int off = 16; off; off >>= 1) {
        s += __shfl_xor_sync(0xffffffffu, s, off);
        r += __shfl_xor_sync(0xffffffffu, r, off);
    }
    if (lane == 0) {
        g_col0[bh * N_ + i] = s;
        g_row0[bh * N_ + i] = r;
    }
}

// ---------------------------------------------------------------------------
// 2D RoPE in place on Q,K for n >= 1.
// dims [0,32): rotate with pos_y ; dims [32,64): rotate with pos_x
// pair (base+i, base+i+16), freq = 100^{-i/16}
// ---------------------------------------------------------------------------
__global__ void rope_kernel(const int* __restrict__ xpos) {
    int b = blockIdx.x;
    int n = blockIdx.y + 1;           // skip cls token
    int h = threadIdx.x >> 5;
    int lane = threadIdx.x & 31;
    int half = lane >> 4;             // 0 -> y, 1 -> x
    int fi = lane & 15;
    float pos = (float)xpos[(b * N_ + n) * 2 + half];
    float inv = powf(100.f, -(float)fi / 16.f);
    float ang = pos * inv;
    float sv, cv;
    sincosf(ang, &sv, &cv);
    size_t base = ((size_t)(b * H_ + h) * N_ + n) * HD_ + half * 32;
    float t1 = g_Q[base + fi], t2 = g_Q[base + fi + 16];
    g_Q[base + fi]      = t1 * cv - t2 * sv;
    g_Q[base + fi + 16] = t2 * cv + t1 * sv;
    t1 = g_K[base + fi]; t2 = g_K[base + fi + 16];
    g_K[base + fi]      = t1 * cv - t2 * sv;
    g_K[base + fi + 16] = t2 * cv + t1 * sv;
}

// ---------------------------------------------------------------------------
// Flash attention: 1 query per thread, 128 queries/block, K/V tiles of 64 in smem.
// score(i,0) overridden with col0; score(0,j) overridden with row0.
// Online softmax with rare-rescale branch.
// ---------------------------------------------------------------------------
constexpr int TKt = 64;

__global__ void __launch_bounds__(128) flash_kernel() {
    const int bh = blockIdx.x;
    const int i = blockIdx.y * 128 + threadIdx.x;
    const bool active = (i < N_);
    const int isafe = active ? i : 0;

    __shared__ float Ks[TKt][HD_];
    __shared__ float Vs[TKt][HD_];

    float q[HD_];
    float acc[HD_];
    const float* Qrow = g_Q + ((size_t)bh * N_ + isafe) * HD_;
    #pragma unroll
    for (int d = 0; d < HD_; d += 4) {
        float4 v = *(const float4*)&Qrow[d];
        q[d] = v.x; q[d + 1] = v.y; q[d + 2] = v.z; q[d + 3] = v.w;
    }
    #pragma unroll
    for (int d = 0; d < HD_; d++) acc[d] = 0.f;
    float mval = -1e30f, l = 0.f;
    const float colv = g_col0[bh * N_ + isafe];
    const float* rowp = g_row0 + bh * N_;

    for (int kt = 0; kt < N_; kt += TKt) {
        int nk = min(TKt, N_ - kt);
        __syncthreads();
        const float* Kg = g_K + ((size_t)bh * N_ + kt) * HD_;
        const float* Vg = g_V + ((size_t)bh * N_ + kt) * HD_;
        for (int t = threadIdx.x; t < nk * (HD_ / 4); t += 128) {
            int j = t >> 4;
            int d = (t & 15) << 2;
            *(float4*)&Ks[j][d] = *(const float4*)&Kg[t * 4];
            *(float4*)&Vs[j][d] = *(const float4*)&Vg[t * 4];
        }
        __syncthreads();
        if (!active) continue;

        for (int j = 0; j < nk; j++) {
            const float* kp = Ks[j];
            float s0 = 0.f, s1 = 0.f, s2 = 0.f, s3 = 0.f;
            #pragma unroll
            for (int d = 0; d < HD_; d += 4) {
                s0 = fmaf(q[d + 0], kp[d + 0], s0);
                s1 = fmaf(q[d + 1], kp[d + 1], s1);
                s2 = fmaf(q[d + 2], kp[d + 2], s2);
                s3 = fmaf(q[d + 3], kp[d + 3], s3);
            }
            float s = (s0 + s1) + (s2 + s3);
            int jj = kt + j;
            if (jj == 0) s = colv;       // unroped q_i . k_cls
            if (i == 0) s = rowp[jj];    // unroped q_cls . k_j
            s *= SCALE;

            const float* vp = Vs[j];
            if (s > mval) {
                float corr = __expf(mval - s);
                mval = s;
                l = l * corr + 1.f;
                #pragma unroll
                for (int d = 0; d < HD_; d++) acc[d] = fmaf(acc[d], corr, vp[d]);
            } else {
                float p = __expf(s - mval);
                l += p;
                #pragma unroll
                for (int d = 0; d < HD_; d++) acc[d] = fmaf(p, vp[d], acc[d]);
            }
        }
    }

    if (active) {
        float inv = 1.f / l;
        int b = bh / H_, h = bh - b * H_;
        float* dst = g_att + ((size_t)(b * N_ + i)) * DIM_ + h * HD_;
        #pragma unroll
        for (int d = 0; d < HD_; d += 4) {
            float4 o;
            o.x = acc[d + 0] * inv; o.y = acc[d + 1] * inv;
            o.z = acc[d + 2] * inv; o.w = acc[d + 3] * inv;
            *(float4*)&dst[d] = o;
        }
    }
}

// ---------------------------------------------------------------------------
extern "C" void kernel_launch(void* const* d_in, const int* in_sizes, int n_in,
                              void* d_out, int out_size) {
    // Locate inputs by element count (robust to scalar-input presence/order)
    int ix = -1, ixpos = -1, iwqkv = -1, iwproj = -1, ibproj = -1;
    for (int k = 0; k < n_in; k++) {
        switch (in_sizes[k]) {
            case NTOK * DIM_:  ix = k; break;       // 6,297,600
            case NTOK * 2:     ixpos = k; break;    // 16,400
            case C3 * DIM_:    iwqkv = k; break;    // 1,769,472
            case DIM_ * DIM_:  iwproj = k; break;   // 589,824
            case DIM_:         ibproj = k; break;   // 768
            default: break;
        }
    }
    const float* x      = (const float*)d_in[ix];
    const int*   xpos   = (const int*)d_in[ixpos];
    const float* w_qkv  = (const float*)d_in[iwqkv];
    const float* w_proj = (const float*)d_in[iwproj];
    const float* b_proj = (const float*)d_in[ibproj];
    float* out = (float*)d_out;

    qkv_gemm_kernel<<<dim3(C3 / BNt, (NTOK + BM - 1) / BM), 256>>>(x, w_qkv);
    cls_kernel<<<dim3(BH, (N_ + 7) / 8), 256>>>();
    rope_kernel<<<dim3(B_, N_ - 1), H_ * 32>>>(xpos);
    flash_kernel<<<dim3(BH, (N_ + 127) / 128), 128>>>();
    proj_gemm_kernel<<<dim3(DIM_ / BNt, (NTOK + BM - 1) / BM), 256>>>(w_proj, b_proj, out);
}

// round 3
// speedup vs baseline: 3.0754x; 3.0754x over previous
#include <cuda_runtime.h>
#include <math.h>
#include <stdint.h>

// Problem constants
constexpr int B_   = 8;
constexpr int N_   = 1025;
constexpr int H_   = 12;
constexpr int HD_  = 64;
constexpr int DIM_ = 768;
constexpr int NTOK = B_ * N_;     // 8200
constexpr int C3   = 3 * DIM_;    // 2304
constexpr int BH   = B_ * H_;     // 96
constexpr float SCALE = 0.125f;   // hd^-0.5

// Scratch
__device__ float g_Q[(size_t)BH * N_ * HD_];
__device__ float g_K[(size_t)BH * N_ * HD_];
__device__ float g_V[(size_t)BH * N_ * HD_];
__device__ float g_col0[BH * N_];              // unroped q_i . k_cls
__device__ float g_row0[BH * N_];              // unroped q_cls . k_j
__device__ float g_att[(size_t)NTOK * DIM_];

// ---------------------------------------------------------------------------
// tf32 helpers
// ---------------------------------------------------------------------------
__device__ __forceinline__ uint32_t f2tf(float f) {
    uint32_t u;
    asm("cvt.rna.tf32.f32 %0, %1;" : "=r"(u) : "f"(f));
    return u;
}

__device__ __forceinline__ void mma_tf32(float* d, const uint32_t* a, const uint32_t* b) {
    asm volatile(
        "mma.sync.aligned.m16n8k8.row.col.f32.tf32.tf32.f32 "
        "{%0,%1,%2,%3}, {%4,%5,%6,%7}, {%8,%9}, {%0,%1,%2,%3};\n"
        : "+f"(d[0]), "+f"(d[1]), "+f"(d[2]), "+f"(d[3])
        : "r"(a[0]), "r"(a[1]), "r"(a[2]), "r"(a[3]), "r"(b[0]), "r"(b[1]));
}

// ---------------------------------------------------------------------------
// tf32 GEMM: C(M x Ncols) = A(M x 768) @ W(Ncols x 768)^T
// BM=64 (4 warps x m16), BN=128 (16 n8 tiles), BK=64. 128 threads.
// MODE 0: A = x (arg), QKV scatter epilogue.
// MODE 1: A = g_att (device symbol, NOT passable from host!), bias + store.
// ---------------------------------------------------------------------------
constexpr int LD = 68;

template <int MODE>
__global__ void __launch_bounds__(128) gemm_tf32_kernel(const float* __restrict__ Aarg,
                                                        const float* __restrict__ W,
                                                        const float* __restrict__ bias,
                                                        float* __restrict__ out,
                                                        int M) {
    extern __shared__ uint32_t sm[];
    uint32_t* As = sm;               // [64][LD]
    uint32_t* Bs = sm + 64 * LD;     // [128][LD]

    // CRITICAL: device globals must be referenced from device code.
    const float* A = (MODE == 0) ? Aarg : (const float*)g_att;

    const int bm = blockIdx.y * 64;
    const int bn = blockIdx.x * 128;
    const int tid = threadIdx.x;
    const int warp = tid >> 5, lane = tid & 31;
    const int g = lane >> 2, t = lane & 3;

    float acc[16][4];
    #pragma unroll
    for (int i = 0; i < 16; i++)
        #pragma unroll
        for (int j = 0; j < 4; j++) acc[i][j] = 0.f;

    for (int k0 = 0; k0 < DIM_; k0 += 64) {
        // Load A tile (64 x 64)
        #pragma unroll
        for (int r = 0; r < 8; r++) {
            int idx = tid + 128 * r;
            int row = idx >> 4;
            int col = (idx & 15) << 2;
            float4 v = make_float4(0.f, 0.f, 0.f, 0.f);
            if (bm + row < M) v = *(const float4*)&A[(size_t)(bm + row) * DIM_ + k0 + col];
            *(uint4*)&As[row * LD + col] =
                make_uint4(f2tf(v.x), f2tf(v.y), f2tf(v.z), f2tf(v.w));
        }
        // Load B tile (128 x 64)  [W rows are the output cols]
        #pragma unroll
        for (int r = 0; r < 16; r++) {
            int idx = tid + 128 * r;
            int row = idx >> 4;
            int col = (idx & 15) << 2;
            float4 v = *(const float4*)&W[(size_t)(bn + row) * DIM_ + k0 + col];
            *(uint4*)&Bs[row * LD + col] =
                make_uint4(f2tf(v.x), f2tf(v.y), f2tf(v.z), f2tf(v.w));
        }
        __syncthreads();

        #pragma unroll
        for (int ks = 0; ks < 8; ks++) {
            const int kc = ks * 8;
            uint32_t a[4];
            const int r0 = warp * 16 + g;
            a[0] = As[r0 * LD + kc + t];
            a[1] = As[(r0 + 8) * LD + kc + t];
            a[2] = As[r0 * LD + kc + t + 4];
            a[3] = As[(r0 + 8) * LD + kc + t + 4];
            #pragma unroll
            for (int nt = 0; nt < 16; nt++) {
                uint32_t b[2];
                const int br = nt * 8 + g;
                b[0] = Bs[br * LD + kc + t];
                b[1] = Bs[br * LD + kc + t + 4];
                mma_tf32(acc[nt], a, b);
            }
        }
        __syncthreads();
    }

    // Epilogue
    const int r0 = bm + warp * 16 + g;
    const int r1 = r0 + 8;
    #pragma unroll
    for (int nt = 0; nt < 16; nt++) {
        const int c0 = bn + nt * 8 + 2 * t;
        if (MODE == 0) {
            // scatter: col = which*768 + h*64 + d
            #pragma unroll
            for (int cc = 0; cc < 2; cc++) {
                int gc = c0 + cc;
                int which = gc / DIM_;
                int rem = gc - which * DIM_;
                int h = rem >> 6, d = rem & 63;
                float* dst = (which == 0) ? g_Q : (which == 1) ? g_K : g_V;
                if (r0 < M) {
                    int b = r0 / N_, n = r0 - b * N_;
                    dst[(size_t)((b * H_ + h) * N_ + n) * HD_ + d] = acc[nt][cc];
                }
                if (r1 < M) {
                    int b = r1 / N_, n = r1 - b * N_;
                    dst[(size_t)((b * H_ + h) * N_ + n) * HD_ + d] = acc[nt][cc + 2];
                }
            }
        } else {
            float bx = bias[c0], by = bias[c0 + 1];
            if (r0 < M) {
                float2 o = make_float2(acc[nt][0] + bx, acc[nt][1] + by);
                *(float2*)&out[(size_t)r0 * DIM_ + c0] = o;
            }
            if (r1 < M) {
                float2 o = make_float2(acc[nt][2] + bx, acc[nt][3] + by);
                *(float2*)&out[(size_t)r1 * DIM_ + c0] = o;
            }
        }
    }
}

// ---------------------------------------------------------------------------
// cls scores (unroped, must run before rope)
// ---------------------------------------------------------------------------
__global__ void __launch_bounds__(256) cls_kernel() {
    int bh = blockIdx.x;
    int warp = threadIdx.x >> 5, lane = threadIdx.x & 31;
    int i = blockIdx.y * 8 + warp;
    if (i >= N_) return;
    const float2* Qi = (const float2*)(g_Q + ((size_t)bh * N_ + i) * HD_);
    const float2* K0 = (const float2*)(g_K + (size_t)bh * N_ * HD_);
    const float2* Q0 = (const float2*)(g_Q + (size_t)bh * N_ * HD_);
    const float2* Ki = (const float2*)(g_K + ((size_t)bh * N_ + i) * HD_);
    float2 a = Qi[lane], b0 = K0[lane], c = Q0[lane], d = Ki[lane];
    float s = a.x * b0.x + a.y * b0.y;
    float r = c.x * d.x + c.y * d.y;
    #pragma unroll
    for (int off = 16; off; off >>= 1) {
        s += __shfl_xor_sync(0xffffffffu, s, off);
        r += __shfl_xor_sync(0xffffffffu, r, off);
    }
    if (lane == 0) {
        g_col0[bh * N_ + i] = s;
        g_row0[bh * N_ + i] = r;
    }
}

// ---------------------------------------------------------------------------
// 2D RoPE in place on Q,K for n >= 1
// ---------------------------------------------------------------------------
__global__ void rope_kernel(const int* __restrict__ xpos) {
    int b = blockIdx.x;
    int n = blockIdx.y + 1;
    int h = threadIdx.x >> 5;
    int lane = threadIdx.x & 31;
    int half = lane >> 4;
    int fi = lane & 15;
    float pos = (float)xpos[(b * N_ + n) * 2 + half];
    float inv = powf(100.f, -(float)fi / 16.f);
    float ang = pos * inv;
    float sv, cv;
    sincosf(ang, &sv, &cv);
    size_t base = ((size_t)(b * H_ + h) * N_ + n) * HD_ + half * 32;
    float t1 = g_Q[base + fi], t2 = g_Q[base + fi + 16];
    g_Q[base + fi]      = t1 * cv - t2 * sv;
    g_Q[base + fi + 16] = t2 * cv + t1 * sv;
    t1 = g_K[base + fi]; t2 = g_K[base + fi + 16];
    g_K[base + fi]      = t1 * cv - t2 * sv;
    g_K[base + fi + 16] = t2 * cv + t1 * sv;
}

// ---------------------------------------------------------------------------
// FlashAttention-2 style, tf32 mma. 64q x 64k tiles, 128 threads (4 warps).
// ---------------------------------------------------------------------------
__global__ void __launch_bounds__(128) flash_tf32_kernel() {
    extern __shared__ uint32_t sm[];
    uint32_t* Qs = sm;                  // [64][LD]
    uint32_t* Ks = Qs + 64 * LD;        // [64][LD]
    uint32_t* Vs = Ks + 64 * LD;        // [64][LD]   V[k][d]
    uint32_t* Ps = Vs + 64 * LD;        // [64][LD]   P[q][k]

    const int bh = blockIdx.x;
    const int qbase = blockIdx.y * 64;
    const int tid = threadIdx.x;
    const int warp = tid >> 5, lane = tid & 31;
    const int g = lane >> 2, t = lane & 3;

    // Load Q tile (rows clamped; padded rows compute garbage, never stored)
    #pragma unroll
    for (int r = 0; r < 8; r++) {
        int idx = tid + 128 * r;
        int row = idx >> 4;
        int col = (idx & 15) << 2;
        int q = min(qbase + row, N_ - 1);
        float4 v = *(const float4*)&g_Q[((size_t)bh * N_ + q) * HD_ + col];
        *(uint4*)&Qs[row * LD + col] =
            make_uint4(f2tf(v.x), f2tf(v.y), f2tf(v.z), f2tf(v.w));
    }

    float oacc[8][4];
    #pragma unroll
    for (int i = 0; i < 8; i++)
        #pragma unroll
        for (int j = 0; j < 4; j++) oacc[i][j] = 0.f;
    float m[2] = {-1e30f, -1e30f};
    float l[2] = {0.f, 0.f};

    const int rq0 = qbase + warp * 16 + g;
    const int rq1 = rq0 + 8;
    const float colv0 = g_col0[bh * N_ + min(rq0, N_ - 1)];
    const float colv1 = g_col0[bh * N_ + min(rq1, N_ - 1)];
    const bool qzero = (rq0 == 0);   // this thread owns global q row 0 (c0,c1)

    for (int kt = 0; kt < 1088; kt += 64) {
        __syncthreads();   // prior PV reads of Ks/Vs/Ps complete
        // Load K,V tiles (zero-fill padded keys)
        #pragma unroll
        for (int r = 0; r < 8; r++) {
            int idx = tid + 128 * r;
            int row = idx >> 4;
            int col = (idx & 15) << 2;
            int k = kt + row;
            float4 kv = make_float4(0.f, 0.f, 0.f, 0.f);
            float4 vv = make_float4(0.f, 0.f, 0.f, 0.f);
            if (k < N_) {
                kv = *(const float4*)&g_K[((size_t)bh * N_ + k) * HD_ + col];
                vv = *(const float4*)&g_V[((size_t)bh * N_ + k) * HD_ + col];
            }
            *(uint4*)&Ks[row * LD + col] =
                make_uint4(f2tf(kv.x), f2tf(kv.y), f2tf(kv.z), f2tf(kv.w));
            *(uint4*)&Vs[row * LD + col] =
                make_uint4(f2tf(vv.x), f2tf(vv.y), f2tf(vv.z), f2tf(vv.w));
        }
        __syncthreads();

        // S = Q . K^T
        float sacc[8][4];
        #pragma unroll
        for (int i = 0; i < 8; i++)
            #pragma unroll
            for (int j = 0; j < 4; j++) sacc[i][j] = 0.f;

        const int pr0 = warp * 16 + g;
        #pragma unroll
        for (int ks = 0; ks < 8; ks++) {
            const int kc = ks * 8;
            uint32_t a[4];
            a[0] = Qs[pr0 * LD + kc + t];
            a[1] = Qs[(pr0 + 8) * LD + kc + t];
            a[2] = Qs[pr0 * LD + kc + t + 4];
            a[3] = Qs[(pr0 + 8) * LD + kc + t + 4];
            #pragma unroll
            for (int nt = 0; nt < 8; nt++) {
                uint32_t b[2];
                const int br = nt * 8 + g;
                b[0] = Ks[br * LD + kc + t];
                b[1] = Ks[br * LD + kc + t + 4];
                mma_tf32(sacc[nt], a, b);
            }
        }

        // masks + cls overrides + scale
        #pragma unroll
        for (int nt = 0; nt < 8; nt++) {
            #pragma unroll
            for (int c = 0; c < 4; c++) {
                int kcol = kt + nt * 8 + 2 * t + (c & 1);
                float s = sacc[nt][c];
                if (kcol >= N_) {
                    s = -1e30f;
                } else {
                    if (kcol == 0) s = (c < 2) ? colv0 : colv1;
                    if (qzero && c < 2) s = g_row0[bh * N_ + kcol];
                    s *= SCALE;
                }
                sacc[nt][c] = s;
            }
        }

        // online softmax per row-half (rows rq0: c0,c1 ; rq1: c2,c3)
        #pragma unroll
        for (int hh = 0; hh < 2; hh++) {
            const int co = 2 * hh;
            float mx = -1e30f;
            #pragma unroll
            for (int nt = 0; nt < 8; nt++)
                mx = fmaxf(mx, fmaxf(sacc[nt][co], sacc[nt][co + 1]));
            mx = fmaxf(mx, __shfl_xor_sync(0xffffffffu, mx, 1));
            mx = fmaxf(mx, __shfl_xor_sync(0xffffffffu, mx, 2));
            float mn = fmaxf(m[hh], mx);
            float corr = __expf(m[hh] - mn);
            m[hh] = mn;
            float ls = 0.f;
            #pragma unroll
            for (int nt = 0; nt < 8; nt++) {
                float p0 = __expf(sacc[nt][co] - mn);
                float p1 = __expf(sacc[nt][co + 1] - mn);
                ls += p0 + p1;
                sacc[nt][co] = p0;
                sacc[nt][co + 1] = p1;
            }
            l[hh] = l[hh] * corr + ls;
            #pragma unroll
            for (int nt = 0; nt < 8; nt++) {
                oacc[nt][co] *= corr;
                oacc[nt][co + 1] *= corr;
            }
        }

        // store P (tf32) to smem: Ps[q][k]
        #pragma unroll
        for (int nt = 0; nt < 8; nt++) {
            int kc = nt * 8 + 2 * t;
            uint2 p0 = make_uint2(f2tf(sacc[nt][0]), f2tf(sacc[nt][1]));
            uint2 p1 = make_uint2(f2tf(sacc[nt][2]), f2tf(sacc[nt][3]));
            *(uint2*)&Ps[pr0 * LD + kc] = p0;
            *(uint2*)&Ps[(pr0 + 8) * LD + kc] = p1;
        }
        __syncthreads();

        // O += P . V
        #pragma unroll
        for (int ks = 0; ks < 8; ks++) {
            const int kc = ks * 8;
            uint32_t a[4];
            a[0] = Ps[pr0 * LD + kc + t];
            a[1] = Ps[(pr0 + 8) * LD + kc + t];
            a[2] = Ps[pr0 * LD + kc + t + 4];
            a[3] = Ps[(pr0 + 8) * LD + kc + t + 4];
            #pragma unroll
            for (int nt = 0; nt < 8; nt++) {
                uint32_t b[2];
                b[0] = Vs[(kc + t) * LD + nt * 8 + g];
                b[1] = Vs[(kc + t + 4) * LD + nt * 8 + g];
                mma_tf32(oacc[nt], a, b);
            }
        }
    }

    // finalize
    #pragma unroll
    for (int hh = 0; hh < 2; hh++) {
        l[hh] += __shfl_xor_sync(0xffffffffu, l[hh], 1);
        l[hh] += __shfl_xor_sync(0xffffffffu, l[hh], 2);
    }
    const float inv0 = 1.f / l[0];
    const float inv1 = 1.f / l[1];
    const int b = bh / H_, h = bh - b * H_;
    #pragma unroll
    for (int nt = 0; nt < 8; nt++) {
        int d = nt * 8 + 2 * t;
        if (rq0 < N_) {
            float2 o = make_float2(oacc[nt][0] * inv0, oacc[nt][1] * inv0);
            *(float2*)&g_att[((size_t)(b * N_ + rq0)) * DIM_ + h * HD_ + d] = o;
        }
        if (rq1 < N_) {
            float2 o = make_float2(oacc[nt][2] * inv1, oacc[nt][3] * inv1);
            *(float2*)&g_att[((size_t)(b * N_ + rq1)) * DIM_ + h * HD_ + d] = o;
        }
    }
}

// ---------------------------------------------------------------------------
constexpr int GEMM_SMEM  = (64 + 128) * LD * 4;   // 52224 B
constexpr int FLASH_SMEM = 4 * 64 * LD * 4;       // 69632 B

extern "C" void kernel_launch(void* const* d_in, const int* in_sizes, int n_in,
                              void* d_out, int out_size) {
    int ix = -1, ixpos = -1, iwqkv = -1, iwproj = -1, ibproj = -1;
    for (int k = 0; k < n_in; k++) {
        switch (in_sizes[k]) {
            case NTOK * DIM_:  ix = k; break;
            case NTOK * 2:     ixpos = k; break;
            case C3 * DIM_:    iwqkv = k; break;
            case DIM_ * DIM_:  iwproj = k; break;
            case DIM_:         ibproj = k; break;
            default: break;
        }
    }
    const float* x      = (const float*)d_in[ix];
    const int*   xpos   = (const int*)d_in[ixpos];
    const float* w_qkv  = (const float*)d_in[iwqkv];
    const float* w_proj = (const float*)d_in[iwproj];
    const float* b_proj = (const float*)d_in[ibproj];
    float* out = (float*)d_out;

    static bool attr_done = false;
    if (!attr_done) {
        cudaFuncSetAttribute(gemm_tf32_kernel<0>, cudaFuncAttributeMaxDynamicSharedMemorySize, GEMM_SMEM);
        cudaFuncSetAttribute(gemm_tf32_kernel<1>, cudaFuncAttributeMaxDynamicSharedMemorySize, GEMM_SMEM);
        cudaFuncSetAttribute(flash_tf32_kernel,   cudaFuncAttributeMaxDynamicSharedMemorySize, FLASH_SMEM);
        attr_done = true;
    }

    const int mtiles = (NTOK + 63) / 64;   // 129

    gemm_tf32_kernel<0><<<dim3(C3 / 128, mtiles), 128, GEMM_SMEM>>>(x, w_qkv, nullptr, nullptr, NTOK);
    cls_kernel<<<dim3(BH, (N_ + 7) / 8), 256>>>();
    rope_kernel<<<dim3(B_, N_ - 1), H_ * 32>>>(xpos);
    flash_tf32_kernel<<<dim3(BH, (N_ + 63) / 64), 128, FLASH_SMEM>>>();
    gemm_tf32_kernel<1><<<dim3(DIM_ / 128, mtiles), 128, GEMM_SMEM>>>(nullptr, w_proj, b_proj, out, NTOK);
}

// round 4
// speedup vs baseline: 3.5915x; 1.1678x over previous
#include <cuda_runtime.h>
#include <math.h>
#include <stdint.h>

// Problem constants
constexpr int B_   = 8;
constexpr int N_   = 1025;
constexpr int H_   = 12;
constexpr int HD_  = 64;
constexpr int DIM_ = 768;
constexpr int NTOK = B_ * N_;     // 8200
constexpr int C3   = 3 * DIM_;    // 2304
constexpr int BH   = B_ * H_;     // 96
constexpr float SCALE = 0.125f;

// Scratch
__device__ float g_Q[(size_t)BH * N_ * HD_];
__device__ float g_K[(size_t)BH * N_ * HD_];
__device__ float g_V[(size_t)BH * N_ * HD_];
__device__ float g_col0[BH * N_];
__device__ float g_row0[BH * N_];
__device__ float g_att[(size_t)NTOK * DIM_];

// ---------------------------------------------------------------------------
__device__ __forceinline__ uint32_t f2tf(float f) {
    uint32_t u;
    asm("cvt.rna.tf32.f32 %0, %1;" : "=r"(u) : "f"(f));
    return u;
}

__device__ __forceinline__ void mma_tf32(float* d, const uint32_t* a, const uint32_t* b) {
    asm volatile(
        "mma.sync.aligned.m16n8k8.row.col.f32.tf32.tf32.f32 "
        "{%0,%1,%2,%3}, {%4,%5,%6,%7}, {%8,%9}, {%0,%1,%2,%3};\n"
        : "+f"(d[0]), "+f"(d[1]), "+f"(d[2]), "+f"(d[3])
        : "r"(a[0]), "r"(a[1]), "r"(a[2]), "r"(a[3]), "r"(b[0]), "r"(b[1]));
}

constexpr int LD  = 68;
constexpr int LDV = 72;   // conflict-free PV B-fragment loads

// ---------------------------------------------------------------------------
// tf32 GEMM: C(M x Ncols) = A(M x 768) @ W(Ncols x 768)^T
// BM=128 (4 warps x m32), BN=128 (16 n8 tiles), BK=64, 128 threads.
// Each warp computes m32 x n128 -> B-fragments amortized over 2 row tiles.
// MODE 0: A = arg, QKV scatter epilogue. MODE 1: A = g_att, bias + store.
// ---------------------------------------------------------------------------
template <int MODE>
__global__ void __launch_bounds__(128) gemm_tf32_kernel(const float* __restrict__ Aarg,
                                                        const float* __restrict__ W,
                                                        const float* __restrict__ bias,
                                                        float* __restrict__ out,
                                                        int M) {
    extern __shared__ uint32_t sm[];
    uint32_t* As = sm;               // [128][LD]
    uint32_t* Bs = sm + 128 * LD;    // [128][LD]

    const float* A = (MODE == 0) ? Aarg : (const float*)g_att;

    const int bm = blockIdx.y * 128;
    const int bn = blockIdx.x * 128;
    const int tid = threadIdx.x;
    const int warp = tid >> 5, lane = tid & 31;
    const int g = lane >> 2, t = lane & 3;

    float acc0[16][4], acc1[16][4];
    #pragma unroll
    for (int i = 0; i < 16; i++)
        #pragma unroll
        for (int j = 0; j < 4; j++) { acc0[i][j] = 0.f; acc1[i][j] = 0.f; }

    for (int k0 = 0; k0 < DIM_; k0 += 64) {
        // Fill A tile (128 x 64) and B tile (128 x 64)
        #pragma unroll
        for (int r = 0; r < 16; r++) {
            int idx = tid + 128 * r;
            int row = idx >> 4;
            int col = (idx & 15) << 2;
            float4 v = make_float4(0.f, 0.f, 0.f, 0.f);
            if (bm + row < M) v = *(const float4*)&A[(size_t)(bm + row) * DIM_ + k0 + col];
            *(uint4*)&As[row * LD + col] =
                make_uint4(f2tf(v.x), f2tf(v.y), f2tf(v.z), f2tf(v.w));
            float4 w = *(const float4*)&W[(size_t)(bn + row) * DIM_ + k0 + col];
            *(uint4*)&Bs[row * LD + col] =
                make_uint4(f2tf(w.x), f2tf(w.y), f2tf(w.z), f2tf(w.w));
        }
        __syncthreads();

        const int r0 = warp * 32 + g;
        #pragma unroll
        for (int ks = 0; ks < 8; ks++) {
            const int kc = ks * 8;
            uint32_t a0[4], a1[4];
            a0[0] = As[(r0 +  0) * LD + kc + t];
            a0[1] = As[(r0 +  8) * LD + kc + t];
            a0[2] = As[(r0 +  0) * LD + kc + t + 4];
            a0[3] = As[(r0 +  8) * LD + kc + t + 4];
            a1[0] = As[(r0 + 16) * LD + kc + t];
            a1[1] = As[(r0 + 24) * LD + kc + t];
            a1[2] = As[(r0 + 16) * LD + kc + t + 4];
            a1[3] = As[(r0 + 24) * LD + kc + t + 4];
            #pragma unroll
            for (int nt = 0; nt < 16; nt++) {
                uint32_t b[2];
                const int br = nt * 8 + g;
                b[0] = Bs[br * LD + kc + t];
                b[1] = Bs[br * LD + kc + t + 4];
                mma_tf32(acc0[nt], a0, b);
                mma_tf32(acc1[nt], a1, b);
            }
        }
        __syncthreads();
    }

    // Epilogue: 4 row positions per thread
    const int rows[4] = { bm + warp * 32 + g,      bm + warp * 32 + g + 8,
                          bm + warp * 32 + g + 16, bm + warp * 32 + g + 24 };
    #pragma unroll
    for (int nt = 0; nt < 16; nt++) {
        const int c0 = bn + nt * 8 + 2 * t;
        float vals[4][2] = {
            {acc0[nt][0], acc0[nt][1]}, {acc0[nt][2], acc0[nt][3]},
            {acc1[nt][0], acc1[nt][1]}, {acc1[nt][2], acc1[nt][3]} };
        if (MODE == 0) {
            #pragma unroll
            for (int cc = 0; cc < 2; cc++) {
                int gc = c0 + cc;
                int which = gc / DIM_;
                int rem = gc - which * DIM_;
                int h = rem >> 6, d = rem & 63;
                float* dst = (which == 0) ? g_Q : (which == 1) ? g_K : g_V;
                #pragma unroll
                for (int rr = 0; rr < 4; rr++) {
                    int gm = rows[rr];
                    if (gm < M) {
                        int b = gm / N_, n = gm - b * N_;
                        dst[(size_t)((b * H_ + h) * N_ + n) * HD_ + d] = vals[rr][cc];
                    }
                }
            }
        } else {
            float bx = bias[c0], by = bias[c0 + 1];
            #pragma unroll
            for (int rr = 0; rr < 4; rr++) {
                int gm = rows[rr];
                if (gm < M) {
                    float2 o = make_float2(vals[rr][0] + bx, vals[rr][1] + by);
                    *(float2*)&out[(size_t)gm * DIM_ + c0] = o;
                }
            }
        }
    }
}

// ---------------------------------------------------------------------------
// cls scores (unroped, before rope)
// ---------------------------------------------------------------------------
__global__ void __launch_bounds__(256) cls_kernel() {
    int bh = blockIdx.x;
    int warp = threadIdx.x >> 5, lane = threadIdx.x & 31;
    int i = blockIdx.y * 8 + warp;
    if (i >= N_) return;
    const float2* Qi = (const float2*)(g_Q + ((size_t)bh * N_ + i) * HD_);
    const float2* K0 = (const float2*)(g_K + (size_t)bh * N_ * HD_);
    const float2* Q0 = (const float2*)(g_Q + (size_t)bh * N_ * HD_);
    const float2* Ki = (const float2*)(g_K + ((size_t)bh * N_ + i) * HD_);
    float2 a = Qi[lane], b0 = K0[lane], c = Q0[lane], d = Ki[lane];
    float s = a.x * b0.x + a.y * b0.y;
    float r = c.x * d.x + c.y * d.y;
    #pragma unroll
    for (int off = 16; off; off >>= 1) {
        s += __shfl_xor_sync(0xffffffffu, s, off);
        r += __shfl_xor_sync(0xffffffffu, r, off);
    }
    if (lane == 0) {
        g_col0[bh * N_ + i] = s;
        g_row0[bh * N_ + i] = r;
    }
}

// ---------------------------------------------------------------------------
// 2D RoPE in place on Q,K for n >= 1
// ---------------------------------------------------------------------------
__global__ void rope_kernel(const int* __restrict__ xpos) {
    int b = blockIdx.x;
    int n = blockIdx.y + 1;
    int h = threadIdx.x >> 5;
    int lane = threadIdx.x & 31;
    int half = lane >> 4;
    int fi = lane & 15;
    float pos = (float)xpos[(b * N_ + n) * 2 + half];
    float inv = powf(100.f, -(float)fi / 16.f);
    float ang = pos * inv;
    float sv, cv;
    sincosf(ang, &sv, &cv);
    size_t base = ((size_t)(b * H_ + h) * N_ + n) * HD_ + half * 32;
    float t1 = g_Q[base + fi], t2 = g_Q[base + fi + 16];
    g_Q[base + fi]      = t1 * cv - t2 * sv;
    g_Q[base + fi + 16] = t2 * cv + t1 * sv;
    t1 = g_K[base + fi]; t2 = g_K[base + fi + 16];
    g_K[base + fi]      = t1 * cv - t2 * sv;
    g_K[base + fi + 16] = t2 * cv + t1 * sv;
}

// ---------------------------------------------------------------------------
// Flash attention, tf32 mma. 128q x 64k tiles, 128 threads (4 warps x m32).
// ---------------------------------------------------------------------------
__global__ void __launch_bounds__(128) flash_tf32_kernel() {
    extern __shared__ uint32_t sm[];
    uint32_t* Qs = sm;                    // [128][LD]
    uint32_t* Ks = Qs + 128 * LD;         // [64][LD]
    uint32_t* Vs = Ks + 64 * LD;          // [64][LDV]  V[k][d]
    uint32_t* Ps = Vs + 64 * LDV;         // [128][LD]  P[q][k]

    const int bh = blockIdx.x;
    const int qbase = blockIdx.y * 128;
    const int tid = threadIdx.x;
    const int warp = tid >> 5, lane = tid & 31;
    const int g = lane >> 2, t = lane & 3;

    // Load Q tile (rows clamped; padded rows compute garbage, never stored)
    #pragma unroll
    for (int r = 0; r < 16; r++) {
        int idx = tid + 128 * r;
        int row = idx >> 4;
        int col = (idx & 15) << 2;
        int q = min(qbase + row, N_ - 1);
        float4 v = *(const float4*)&g_Q[((size_t)bh * N_ + q) * HD_ + col];
        *(uint4*)&Qs[row * LD + col] =
            make_uint4(f2tf(v.x), f2tf(v.y), f2tf(v.z), f2tf(v.w));
    }

    float oacc0[8][4], oacc1[8][4];
    #pragma unroll
    for (int i = 0; i < 8; i++)
        #pragma unroll
        for (int j = 0; j < 4; j++) { oacc0[i][j] = 0.f; oacc1[i][j] = 0.f; }
    float m[4] = {-1e30f, -1e30f, -1e30f, -1e30f};
    float l[4] = {0.f, 0.f, 0.f, 0.f};

    const int pr0 = warp * 32 + g;               // local row of tile A lower half
    const int rq[4] = { qbase + pr0, qbase + pr0 + 8,
                        qbase + pr0 + 16, qbase + pr0 + 24 };
    float colv[4];
    #pragma unroll
    for (int rr = 0; rr < 4; rr++) colv[rr] = g_col0[bh * N_ + min(rq[rr], N_ - 1)];
    const bool qzero = (rq[0] == 0);

    for (int kt = 0; kt < 1088; kt += 64) {
        __syncthreads();
        // Fill K (LD) and V (LDV) tiles; zero-pad beyond N
        #pragma unroll
        for (int r = 0; r < 8; r++) {
            int idx = tid + 128 * r;
            int row = idx >> 4;
            int col = (idx & 15) << 2;
            int k = kt + row;
            float4 kv = make_float4(0.f, 0.f, 0.f, 0.f);
            float4 vv = make_float4(0.f, 0.f, 0.f, 0.f);
            if (k < N_) {
                kv = *(const float4*)&g_K[((size_t)bh * N_ + k) * HD_ + col];
                vv = *(const float4*)&g_V[((size_t)bh * N_ + k) * HD_ + col];
            }
            *(uint4*)&Ks[row * LD + col] =
                make_uint4(f2tf(kv.x), f2tf(kv.y), f2tf(kv.z), f2tf(kv.w));
            *(uint4*)&Vs[row * LDV + col] =
                make_uint4(f2tf(vv.x), f2tf(vv.y), f2tf(vv.z), f2tf(vv.w));
        }
        __syncthreads();

        // S = Q . K^T  (two m16 row tiles per warp share B fragments)
        float sacc0[8][4], sacc1[8][4];
        #pragma unroll
        for (int i = 0; i < 8; i++)
            #pragma unroll
            for (int j = 0; j < 4; j++) { sacc0[i][j] = 0.f; sacc1[i][j] = 0.f; }

        #pragma unroll
        for (int ks = 0; ks < 8; ks++) {
            const int kc = ks * 8;
            uint32_t a0[4], a1[4];
            a0[0] = Qs[(pr0 +  0) * LD + kc + t];
            a0[1] = Qs[(pr0 +  8) * LD + kc + t];
            a0[2] = Qs[(pr0 +  0) * LD + kc + t + 4];
            a0[3] = Qs[(pr0 +  8) * LD + kc + t + 4];
            a1[0] = Qs[(pr0 + 16) * LD + kc + t];
            a1[1] = Qs[(pr0 + 24) * LD + kc + t];
            a1[2] = Qs[(pr0 + 16) * LD + kc + t + 4];
            a1[3] = Qs[(pr0 + 24) * LD + kc + t + 4];
            #pragma unroll
            for (int nt = 0; nt < 8; nt++) {
                uint32_t b[2];
                const int br = nt * 8 + g;
                b[0] = Ks[br * LD + kc + t];
                b[1] = Ks[br * LD + kc + t + 4];
                mma_tf32(sacc0[nt], a0, b);
                mma_tf32(sacc1[nt], a1, b);
            }
        }

        // masks + cls overrides + scale
        #pragma unroll
        for (int nt = 0; nt < 8; nt++) {
            #pragma unroll
            for (int c = 0; c < 4; c++) {
                int kcol = kt + nt * 8 + 2 * t + (c & 1);
                float s0 = sacc0[nt][c];
                float s1 = sacc1[nt][c];
                if (kcol >= N_) {
                    s0 = -1e30f; s1 = -1e30f;
                } else {
                    if (kcol == 0) {
                        s0 = (c < 2) ? colv[0] : colv[1];
                        s1 = (c < 2) ? colv[2] : colv[3];
                    }
                    if (qzero && c < 2) s0 = g_row0[bh * N_ + kcol];
                    s0 *= SCALE; s1 *= SCALE;
                }
                sacc0[nt][c] = s0;
                sacc1[nt][c] = s1;
            }
        }

        // online softmax: 4 row-halves
        #pragma unroll
        for (int hh = 0; hh < 4; hh++) {
            float (*sa)[4] = (hh < 2) ? sacc0 : sacc1;
            float (*oa)[4] = (hh < 2) ? oacc0 : oacc1;
            const int co = (hh & 1) * 2;
            float mx = -1e30f;
            #pragma unroll
            for (int nt = 0; nt < 8; nt++)
                mx = fmaxf(mx, fmaxf(sa[nt][co], sa[nt][co + 1]));
            mx = fmaxf(mx, __shfl_xor_sync(0xffffffffu, mx, 1));
            mx = fmaxf(mx, __shfl_xor_sync(0xffffffffu, mx, 2));
            float mn = fmaxf(m[hh], mx);
            float corr = __expf(m[hh] - mn);
            m[hh] = mn;
            float ls = 0.f;
            #pragma unroll
            for (int nt = 0; nt < 8; nt++) {
                float p0 = __expf(sa[nt][co] - mn);
                float p1 = __expf(sa[nt][co + 1] - mn);
                ls += p0 + p1;
                sa[nt][co] = p0;
                sa[nt][co + 1] = p1;
            }
            l[hh] = l[hh] * corr + ls;
            #pragma unroll
            for (int nt = 0; nt < 8; nt++) {
                oa[nt][co] *= corr;
                oa[nt][co + 1] *= corr;
            }
        }

        // store P (tf32) to smem
        #pragma unroll
        for (int nt = 0; nt < 8; nt++) {
            int kc = nt * 8 + 2 * t;
            *(uint2*)&Ps[(pr0 +  0) * LD + kc] = make_uint2(f2tf(sacc0[nt][0]), f2tf(sacc0[nt][1]));
            *(uint2*)&Ps[(pr0 +  8) * LD + kc] = make_uint2(f2tf(sacc0[nt][2]), f2tf(sacc0[nt][3]));
            *(uint2*)&Ps[(pr0 + 16) * LD + kc] = make_uint2(f2tf(sacc1[nt][0]), f2tf(sacc1[nt][1]));
            *(uint2*)&Ps[(pr0 + 24) * LD + kc] = make_uint2(f2tf(sacc1[nt][2]), f2tf(sacc1[nt][3]));
        }
        __syncwarp();

        // O += P . V   (B fragments from Vs shared across both row tiles)
        #pragma unroll
        for (int ks = 0; ks < 8; ks++) {
            const int kc = ks * 8;
            uint32_t a0[4], a1[4];
            a0[0] = Ps[(pr0 +  0) * LD + kc + t];
            a0[1] = Ps[(pr0 +  8) * LD + kc + t];
            a0[2] = Ps[(pr0 +  0) * LD + kc + t + 4];
            a0[3] = Ps[(pr0 +  8) * LD + kc + t + 4];
            a1[0] = Ps[(pr0 + 16) * LD + kc + t];
            a1[1] = Ps[(pr0 + 24) * LD + kc + t];
            a1[2] = Ps[(pr0 + 16) * LD + kc + t + 4];
            a1[3] = Ps[(pr0 + 24) * LD + kc + t + 4];
            #pragma unroll
            for (int nt = 0; nt < 8; nt++) {
                uint32_t b[2];
                b[0] = Vs[(kc + t) * LDV + nt * 8 + g];
                b[1] = Vs[(kc + t + 4) * LDV + nt * 8 + g];
                mma_tf32(oacc0[nt], a0, b);
                mma_tf32(oacc1[nt], a1, b);
            }
        }
    }

    // finalize
    #pragma unroll
    for (int hh = 0; hh < 4; hh++) {
        l[hh] += __shfl_xor_sync(0xffffffffu, l[hh], 1);
        l[hh] += __shfl_xor_sync(0xffffffffu, l[hh], 2);
        l[hh] = 1.f / l[hh];
    }
    const int b = bh / H_, h = bh - b * H_;
    #pragma unroll
    for (int nt = 0; nt < 8; nt++) {
        int d = nt * 8 + 2 * t;
        float vals[4][2] = {
            {oacc0[nt][0], oacc0[nt][1]}, {oacc0[nt][2], oacc0[nt][3]},
            {oacc1[nt][0], oacc1[nt][1]}, {oacc1[nt][2], oacc1[nt][3]} };
        #pragma unroll
        for (int rr = 0; rr < 4; rr++) {
            if (rq[rr] < N_) {
                float2 o = make_float2(vals[rr][0] * l[rr], vals[rr][1] * l[rr]);
                *(float2*)&g_att[((size_t)(b * N_ + rq[rr])) * DIM_ + h * HD_ + d] = o;
            }
        }
    }
}

// ---------------------------------------------------------------------------
constexpr int GEMM_SMEM  = 256 * LD * 4;                               // 69632
constexpr int FLASH_SMEM = (128 * LD + 64 * LD + 64 * LDV + 128 * LD) * 4;  // 105472

extern "C" void kernel_launch(void* const* d_in, const int* in_sizes, int n_in,
                              void* d_out, int out_size) {
    int ix = -1, ixpos = -1, iwqkv = -1, iwproj = -1, ibproj = -1;
    for (int k = 0; k < n_in; k++) {
        switch (in_sizes[k]) {
            case NTOK * DIM_:  ix = k; break;
            case NTOK * 2:     ixpos = k; break;
            case C3 * DIM_:    iwqkv = k; break;
            case DIM_ * DIM_:  iwproj = k; break;
            case DIM_:         ibproj = k; break;
            default: break;
        }
    }
    const float* x      = (const float*)d_in[ix];
    const int*   xpos   = (const int*)d_in[ixpos];
    const float* w_qkv  = (const float*)d_in[iwqkv];
    const float* w_proj = (const float*)d_in[iwproj];
    const float* b_proj = (const float*)d_in[ibproj];
    float* out = (float*)d_out;

    cudaFuncSetAttribute(gemm_tf32_kernel<0>, cudaFuncAttributeMaxDynamicSharedMemorySize, GEMM_SMEM);
    cudaFuncSetAttribute(gemm_tf32_kernel<1>, cudaFuncAttributeMaxDynamicSharedMemorySize, GEMM_SMEM);
    cudaFuncSetAttribute(flash_tf32_kernel,   cudaFuncAttributeMaxDynamicSharedMemorySize, FLASH_SMEM);

    const int mtiles = (NTOK + 127) / 128;   // 65

    gemm_tf32_kernel<0><<<dim3(C3 / 128, mtiles), 128, GEMM_SMEM>>>(x, w_qkv, nullptr, nullptr, NTOK);
    cls_kernel<<<dim3(BH, (N_ + 7) / 8), 256>>>();
    rope_kernel<<<dim3(B_, N_ - 1), H_ * 32>>>(xpos);
    flash_tf32_kernel<<<dim3(BH, (N_ + 127) / 128), 128, FLASH_SMEM>>>();
    gemm_tf32_kernel<1><<<dim3(DIM_ / 128, mtiles), 128, GEMM_SMEM>>>(nullptr, w_proj, b_proj, out, NTOK);
}